// round 11
// baseline (speedup 1.0000x reference)
#include <cuda_runtime.h>
#include <cstdint>

// ---------------- problem dims ----------------
static constexpr int N_ROWS = 8192;    // samples
static constexpr int C_CLS  = 1000;    // classes
static constexpr int D_DIM  = 10000;   // hypervector dim
static constexpr int D_PAD  = 10240;   // padded: 160 * 64 (zeros contribute 0 to dot)
static constexpr int C_PAD  = 1024;    // padded classes (rows >= 1000 are zero)

// ---------------- GEMM tiling (bf16) ----------------
static constexpr int BM = 128;
static constexpr int BN = 128;
static constexpr int BK = 64;               // 64 bf16 = 128B rows
static constexpr int KT = D_PAD / BK;       // 160 total K-iterations
static constexpr int KSPLIT = 2;
static constexpr int KT_HALF = KT / KSPLIT; // 80 per z-slice
static constexpr int STAGES = 3;

static constexpr int A_BYTES = BM * BK * 2;            // 16384
static constexpr int STAGE_BYTES = (BM + BN) * BK * 2; // 32768
static constexpr int SMEM_TOTAL = STAGES * STAGE_BYTES; // 98304 -> 2 CTAs/SM

// ---------------- scratch (device globals; no allocation allowed) ----------
__device__ uint16_t g_A[(size_t)N_ROWS * D_PAD];        // 168 MB bf16 {0,1}
__device__ uint16_t g_B[(size_t)C_PAD  * D_PAD];        // 21 MB bf16, holds 1-2*B
__device__ float    g_part[(size_t)KSPLIT * N_ROWS * C_PAD];  // 67 MB partials
__device__ int g_csum[C_PAD];

// ---------------- helpers ----------------
__device__ __forceinline__ uint32_t smem_to_u32(const void* p) {
    uint32_t a;
    asm("{ .reg .u64 t; cvta.to.shared.u64 t, %1; cvt.u32.u64 %0, t; }" : "=r"(a) : "l"(p));
    return a;
}

__device__ __forceinline__ void cp_async16(uint32_t smem_addr, const void* gptr) {
    asm volatile("cp.async.cg.shared.global [%0], [%1], 16;"
                 :: "r"(smem_addr), "l"(gptr) : "memory");
}
#define CP_COMMIT() asm volatile("cp.async.commit_group;" ::: "memory")
#define CP_WAIT1()  asm volatile("cp.async.wait_group 1;" ::: "memory")

#define LDSM_X4(r0, r1, r2, r3, addr) \
    asm volatile("ldmatrix.sync.aligned.m8n8.x4.shared.b16 {%0,%1,%2,%3}, [%4];" \
                 : "=r"(r0), "=r"(r1), "=r"(r2), "=r"(r3) : "r"(addr))

// bf16 MMA, fp32 accumulate: D += A(16x16) * B(16x8)^T
#define MMA_BF16(d, a, b) \
    asm volatile("mma.sync.aligned.m16n8k16.row.col.f32.bf16.bf16.f32 " \
                 "{%0,%1,%2,%3}, {%4,%5,%6,%7}, {%8,%9}, {%0,%1,%2,%3};" \
                 : "+f"((d)[0]), "+f"((d)[1]), "+f"((d)[2]), "+f"((d)[3]) \
                 : "r"((a)[0]), "r"((a)[1]), "r"((a)[2]), "r"((a)[3]), \
                   "r"((b)[0]), "r"((b)[1]))

// pack two floats into one u32 holding two bf16 (exact for {-1,0,1})
__device__ __forceinline__ uint32_t packbf2(float lo, float hi) {
    return __byte_perm(__float_as_uint(lo), __float_as_uint(hi), 0x7632);
}

// ---------------- conversion A: fp32 {0,1} -> bf16 ----
__global__ void __launch_bounds__(256) cvt_a_kernel(const float* __restrict__ src) {
    const int row = blockIdx.x;       // 0..8191
    const int tid = threadIdx.x;
    uint4* d4 = reinterpret_cast<uint4*>(g_A + (size_t)row * D_PAD);  // 16B = 8 bf16
    const float4* s4 = reinterpret_cast<const float4*>(src + (size_t)row * D_DIM);
    for (int i = tid; i < D_PAD / 8; i += 256) {
        uint4 o;
        if (i < D_DIM / 8) {
            float4 v0 = s4[i * 2 + 0];
            float4 v1 = s4[i * 2 + 1];
            o.x = packbf2(v0.x, v0.y);
            o.y = packbf2(v0.z, v0.w);
            o.z = packbf2(v1.x, v1.y);
            o.w = packbf2(v1.z, v1.w);
        } else { o.x = 0u; o.y = 0u; o.z = 0u; o.w = 0u; }
        d4[i] = o;
    }
}

// ---------------- conversion B: {0,1} -> bf16(1-2B) in {-1,+1}, + csum ----
__global__ void __launch_bounds__(256) cvt_b_kernel(const float* __restrict__ src) {
    const int row = blockIdx.x;       // 0..1023
    const int tid = threadIdx.x;
    int acc = 0;
    uint4* d4 = reinterpret_cast<uint4*>(g_B + (size_t)row * D_PAD);
    if (row < C_CLS) {
        const float4* s4 = reinterpret_cast<const float4*>(src + (size_t)row * D_DIM);
        for (int i = tid; i < D_PAD / 8; i += 256) {
            uint4 o;
            if (i < D_DIM / 8) {
                float4 v0 = s4[i * 2 + 0];
                float4 v1 = s4[i * 2 + 1];
                float fs = v0.x + v0.y + v0.z + v0.w + v1.x + v1.y + v1.z + v1.w;
                acc += (int)fs;   // csum: exact
                o.x = packbf2(1.0f - 2.0f * v0.x, 1.0f - 2.0f * v0.y);
                o.y = packbf2(1.0f - 2.0f * v0.z, 1.0f - 2.0f * v0.w);
                o.z = packbf2(1.0f - 2.0f * v1.x, 1.0f - 2.0f * v1.y);
                o.w = packbf2(1.0f - 2.0f * v1.z, 1.0f - 2.0f * v1.w);
            } else { o.x = 0u; o.y = 0u; o.z = 0u; o.w = 0u; }  // pad MUST be 0
            d4[i] = o;
        }
    } else {
        uint4 z; z.x = 0u; z.y = 0u; z.z = 0u; z.w = 0u;
        for (int i = tid; i < D_PAD / 8; i += 256) d4[i] = z;
    }
    __shared__ int red[8];
    for (int off = 16; off > 0; off >>= 1) acc += __shfl_xor_sync(0xffffffffu, acc, off);
    if ((tid & 31) == 0) red[tid >> 5] = acc;
    __syncthreads();
    if (tid < 8) {
        int v = red[tid];
        for (int off = 4; off > 0; off >>= 1) v += __shfl_xor_sync(0xffu, v, off);
        if (tid == 0) g_csum[row] = v;
    }
}

// ---------------- bf16 GEMM (K-split), partials to g_part ----------------
// Block tile 128x128, 256 threads = 8 warps arranged 4 (M) x 2 (N);
// warp tile 32x64. blockIdx.z selects K-half. 2 CTAs/SM, 1024 CTAs.
__global__ void __launch_bounds__(256, 2) hd_gemm_kernel() {
    extern __shared__ char smem[];
    const uint32_t smem_base = smem_to_u32(smem);
    const int tid = threadIdx.x;
    const int wid = tid >> 5;
    const int lane = tid & 31;
    const int wm = wid & 3;     // 0..3  (M: 32 rows each)
    const int wn = wid >> 2;    // 0..1  (N: 64 cols each)
    const int colTile = blockIdx.x;   // 0..7
    const int rowTile = blockIdx.y;   // 0..63
    const int kz = blockIdx.z;        // 0..1
    const int ktBeg = kz * KT_HALF;

    const uint16_t* aG = g_A + (size_t)rowTile * BM * D_PAD;
    const uint16_t* bG = g_B + (size_t)colTile * BN * D_PAD;

    // loader: 256 threads x 8 iters x 16B. smem rows 0..127 = A, 128..255 = B.
    const int lr = tid >> 3;   // base row 0..31 (stride 32)
    const int lc = tid & 7;    // 16B chunk 0..7 within 128B row

    auto load_stage = [&](int kt, int s) {
        const uint32_t stBase = smem_base + s * STAGE_BYTES;
        const size_t gchunk = (size_t)kt * 8 + lc;   // 16B chunks; row = 1280 chunks
#pragma unroll
        for (int i = 0; i < 8; ++i) {
            const int r = lr + 32 * i;               // 0..255
            const uint32_t off = (uint32_t)(r * 128 + ((lc ^ (r & 7)) << 4));
            const char* src = (r < BM)
                ? reinterpret_cast<const char*>(aG) + ((size_t)r * 1280 + gchunk) * 16
                : reinterpret_cast<const char*>(bG) + ((size_t)(r - BM) * 1280 + gchunk) * 16;
            cp_async16(stBase + off, src);
        }
    };

    // ldmatrix lane addressing (validated R10 32x64-warp scheme)
    const int aLane16 = lane & 15;
    const int aTop = lane >> 4;              // chunk offset 0/1 within the 32B k16
    uint32_t aRowOff[2]; int aXor[2];
#pragma unroll
    for (int mt = 0; mt < 2; ++mt) {
        const int r = wm * 32 + mt * 16 + aLane16;      // A rows 0..127
        aRowOff[mt] = (uint32_t)(r * 128);
        aXor[mt] = r & 7;
    }
    const int bRowInTile = ((lane & 16) >> 1) + (lane & 7);  // +8 for lanes>=16
    const int bTop = (lane >> 3) & 1;        // chunk offset 0/1
    uint32_t bRowOff[4]; int bXor[4];
#pragma unroll
    for (int p = 0; p < 4; ++p) {
        const int r = wn * 64 + p * 16 + bRowInTile;    // B rows 0..127
        bRowOff[p] = (uint32_t)(r * 128);
        bXor[p] = r & 7;
    }

    float acc[2][8][4];
#pragma unroll
    for (int mt = 0; mt < 2; ++mt)
#pragma unroll
        for (int nt = 0; nt < 8; ++nt)
#pragma unroll
            for (int q = 0; q < 4; ++q) acc[mt][nt][q] = 0.0f;

    // prologue: 2 stages in flight
    load_stage(ktBeg + 0, 0); CP_COMMIT();
    load_stage(ktBeg + 1, 1); CP_COMMIT();

    for (int kk = 0; kk < KT_HALF; ++kk) {
        CP_WAIT1();
        __syncthreads();
        if (kk + 2 < KT_HALF) load_stage(ktBeg + kk + 2, (kk + 2) % STAGES);
        CP_COMMIT();

        const uint32_t aBase = smem_base + (kk % STAGES) * STAGE_BYTES;
        const uint32_t bBase = aBase + A_BYTES;
#pragma unroll
        for (int ks = 0; ks < 4; ++ks) {     // 4 x k16 within BK=64
            uint32_t af[2][4];
#pragma unroll
            for (int mt = 0; mt < 2; ++mt) {
                const int chunk = ks * 2 + aTop;
                const uint32_t addr = aBase + aRowOff[mt] + (uint32_t)((chunk ^ aXor[mt]) << 4);
                LDSM_X4(af[mt][0], af[mt][1], af[mt][2], af[mt][3], addr);
            }
            uint32_t bf[8][2];
#pragma unroll
            for (int p = 0; p < 4; ++p) {
                const int chunk = ks * 2 + bTop;
                const uint32_t addr = bBase + bRowOff[p] + (uint32_t)((chunk ^ bXor[p]) << 4);
                LDSM_X4(bf[2 * p][0], bf[2 * p][1], bf[2 * p + 1][0], bf[2 * p + 1][1], addr);
            }
#pragma unroll
            for (int mt = 0; mt < 2; ++mt)
#pragma unroll
                for (int nt = 0; nt < 8; ++nt)
                    MMA_BF16(acc[mt][nt], af[mt], bf[nt]);
        }
    }

    // ---------------- epilogue: store fp32 partials (exact ints) ----
    float* part = g_part + (size_t)kz * N_ROWS * C_PAD;
    const int groupID = lane >> 2;   // 0..7
    const int tig = lane & 3;        // 0..3
#pragma unroll
    for (int mt = 0; mt < 2; ++mt) {
        const int m0 = rowTile * BM + wm * 32 + mt * 16 + groupID;
        float* prow0 = part + (size_t)m0 * C_PAD;
        float* prow1 = part + (size_t)(m0 + 8) * C_PAD;
#pragma unroll
        for (int nt = 0; nt < 8; ++nt) {
            const int c0 = colTile * BN + wn * 64 + nt * 8 + 2 * tig;
            float2 v0, v1;
            v0.x = acc[mt][nt][0]; v0.y = acc[mt][nt][1];
            v1.x = acc[mt][nt][2]; v1.y = acc[mt][nt][3];
            *reinterpret_cast<float2*>(prow0 + c0) = v0;
            *reinterpret_cast<float2*>(prow1 + c0) = v1;
        }
    }
}

// ---------------- combine: out = csum + p0 + p1 ----------------
__global__ void __launch_bounds__(256) combine_kernel(float* __restrict__ out) {
    const int n = blockIdx.x;         // 0..8191
    const int tid = threadIdx.x;
    const float4* p0 = reinterpret_cast<const float4*>(g_part + (size_t)n * C_PAD);
    const float4* p1 = reinterpret_cast<const float4*>(
        g_part + (size_t)(N_ROWS + n) * C_PAD);
    float4* orow = reinterpret_cast<float4*>(out + (size_t)n * C_CLS);
    if (tid < C_CLS / 4) {            // 250 float4 per row
        const int c = tid * 4;
        float4 a = p0[tid];
        float4 b = p1[tid];
        float4 o;
        o.x = (float)g_csum[c + 0] + a.x + b.x;
        o.y = (float)g_csum[c + 1] + a.y + b.y;
        o.z = (float)g_csum[c + 2] + a.z + b.z;
        o.w = (float)g_csum[c + 3] + a.w + b.w;
        orow[tid] = o;
    }
}

// ---------------- launch ----------------
extern "C" void kernel_launch(void* const* d_in, const int* in_sizes, int n_in,
                              void* d_out, int out_size) {
    const float* samples = (const float*)d_in[0];   // [8192, 10000]
    const float* classes = (const float*)d_in[1];   // [1000, 10000]
    float* out = (float*)d_out;                     // [8192, 1000]

    cudaFuncSetAttribute(hd_gemm_kernel, cudaFuncAttributeMaxDynamicSharedMemorySize,
                         SMEM_TOTAL);

    cvt_b_kernel<<<C_PAD, 256>>>(classes);
    cvt_a_kernel<<<N_ROWS, 256>>>(samples);

    dim3 grid(C_PAD / BN, N_ROWS / BM, KSPLIT);  // (8, 64, 2) = 1024 CTAs
    hd_gemm_kernel<<<grid, 256, SMEM_TOTAL>>>();

    combine_kernel<<<N_ROWS, 256>>>(out);
}

// round 12
// speedup vs baseline: 1.0014x; 1.0014x over previous
#include <cuda_runtime.h>
#include <cstdint>

// ---------------- problem dims ----------------
static constexpr int N_ROWS = 8192;    // samples
static constexpr int C_CLS  = 1000;    // classes
static constexpr int D_DIM  = 10000;   // hypervector dim
static constexpr int D_PAD  = 10240;   // padded: 160 * 64 (zeros contribute 0 to dot)
static constexpr int C_PAD  = 1024;    // padded classes (rows >= 1000 are zero)

// ---------------- GEMM tiling (bf16) ----------------
static constexpr int BM = 128;
static constexpr int BN = 128;
static constexpr int BK = 64;               // 64 bf16 = 128B rows
static constexpr int KT = D_PAD / BK;       // 160 total K-iterations
static constexpr int KSPLIT = 2;
static constexpr int KT_HALF = KT / KSPLIT; // 80 per z-slice
static constexpr int STAGES = 3;

static constexpr int A_BYTES = BM * BK * 2;            // 16384
static constexpr int STAGE_BYTES = (BM + BN) * BK * 2; // 32768
static constexpr int SMEM_TOTAL = STAGES * STAGE_BYTES; // 98304 -> 2 CTAs/SM

// ---------------- scratch (device globals; no allocation allowed) ----------
__device__ uint16_t g_A[(size_t)N_ROWS * D_PAD];        // 168 MB bf16 {0,1}
__device__ uint16_t g_B[(size_t)C_PAD  * D_PAD];        // 21 MB bf16, holds 1-2*B
__device__ float    g_part[(size_t)KSPLIT * N_ROWS * C_PAD];  // 67 MB partials
__device__ int g_csum[C_PAD];

// ---------------- helpers ----------------
__device__ __forceinline__ uint32_t smem_to_u32(const void* p) {
    uint32_t a;
    asm("{ .reg .u64 t; cvta.to.shared.u64 t, %1; cvt.u32.u64 %0, t; }" : "=r"(a) : "l"(p));
    return a;
}

__device__ __forceinline__ void cp_async16(uint32_t smem_addr, const void* gptr) {
    asm volatile("cp.async.cg.shared.global [%0], [%1], 16;"
                 :: "r"(smem_addr), "l"(gptr) : "memory");
}
#define CP_COMMIT() asm volatile("cp.async.commit_group;" ::: "memory")
#define CP_WAIT1()  asm volatile("cp.async.wait_group 1;" ::: "memory")

#define LDSM_X4(r0, r1, r2, r3, addr) \
    asm volatile("ldmatrix.sync.aligned.m8n8.x4.shared.b16 {%0,%1,%2,%3}, [%4];" \
                 : "=r"(r0), "=r"(r1), "=r"(r2), "=r"(r3) : "r"(addr))

// bf16 MMA, fp32 accumulate: D += A(16x16) * B(16x8)^T
#define MMA_BF16(d, a, b) \
    asm volatile("mma.sync.aligned.m16n8k16.row.col.f32.bf16.bf16.f32 " \
                 "{%0,%1,%2,%3}, {%4,%5,%6,%7}, {%8,%9}, {%0,%1,%2,%3};" \
                 : "+f"((d)[0]), "+f"((d)[1]), "+f"((d)[2]), "+f"((d)[3]) \
                 : "r"((a)[0]), "r"((a)[1]), "r"((a)[2]), "r"((a)[3]), \
                   "r"((b)[0]), "r"((b)[1]))

// pack two floats into one u32 holding two bf16 (exact for {-1,0,1})
__device__ __forceinline__ uint32_t packbf2(float lo, float hi) {
    return __byte_perm(__float_as_uint(lo), __float_as_uint(hi), 0x7632);
}

// ---------------- conversion A: fp32 {0,1} -> bf16 ----
__global__ void __launch_bounds__(256) cvt_a_kernel(const float* __restrict__ src) {
    const int row = blockIdx.x;       // 0..8191
    const int tid = threadIdx.x;
    uint4* d4 = reinterpret_cast<uint4*>(g_A + (size_t)row * D_PAD);  // 16B = 8 bf16
    const float4* s4 = reinterpret_cast<const float4*>(src + (size_t)row * D_DIM);
    for (int i = tid; i < D_PAD / 8; i += 256) {
        uint4 o;
        if (i < D_DIM / 8) {
            float4 v0 = s4[i * 2 + 0];
            float4 v1 = s4[i * 2 + 1];
            o.x = packbf2(v0.x, v0.y);
            o.y = packbf2(v0.z, v0.w);
            o.z = packbf2(v1.x, v1.y);
            o.w = packbf2(v1.z, v1.w);
        } else { o.x = 0u; o.y = 0u; o.z = 0u; o.w = 0u; }
        d4[i] = o;
    }
}

// ---------------- conversion B: {0,1} -> bf16(1-2B) in {-1,+1}, + csum ----
__global__ void __launch_bounds__(256) cvt_b_kernel(const float* __restrict__ src) {
    const int row = blockIdx.x;       // 0..1023
    const int tid = threadIdx.x;
    int acc = 0;
    uint4* d4 = reinterpret_cast<uint4*>(g_B + (size_t)row * D_PAD);
    if (row < C_CLS) {
        const float4* s4 = reinterpret_cast<const float4*>(src + (size_t)row * D_DIM);
        for (int i = tid; i < D_PAD / 8; i += 256) {
            uint4 o;
            if (i < D_DIM / 8) {
                float4 v0 = s4[i * 2 + 0];
                float4 v1 = s4[i * 2 + 1];
                float fs = v0.x + v0.y + v0.z + v0.w + v1.x + v1.y + v1.z + v1.w;
                acc += (int)fs;   // csum: exact
                o.x = packbf2(1.0f - 2.0f * v0.x, 1.0f - 2.0f * v0.y);
                o.y = packbf2(1.0f - 2.0f * v0.z, 1.0f - 2.0f * v0.w);
                o.z = packbf2(1.0f - 2.0f * v1.x, 1.0f - 2.0f * v1.y);
                o.w = packbf2(1.0f - 2.0f * v1.z, 1.0f - 2.0f * v1.w);
            } else { o.x = 0u; o.y = 0u; o.z = 0u; o.w = 0u; }  // pad MUST be 0
            d4[i] = o;
        }
    } else {
        uint4 z; z.x = 0u; z.y = 0u; z.z = 0u; z.w = 0u;
        for (int i = tid; i < D_PAD / 8; i += 256) d4[i] = z;
    }
    __shared__ int red[8];
    for (int off = 16; off > 0; off >>= 1) acc += __shfl_xor_sync(0xffffffffu, acc, off);
    if ((tid & 31) == 0) red[tid >> 5] = acc;
    __syncthreads();
    if (tid < 8) {
        int v = red[tid];
        for (int off = 4; off > 0; off >>= 1) v += __shfl_xor_sync(0xffu, v, off);
        if (tid == 0) g_csum[row] = v;
    }
}

// ---------------- bf16 GEMM (K-split), partials to g_part ----------------
// Block tile 128x128, 128 threads = 4 warps arranged 2 (M) x 2 (N);
// warp tile 64x64 -> minimal smem crossbar traffic. 2 CTAs/SM, 1024 CTAs.
__global__ void __launch_bounds__(128, 2) hd_gemm_kernel() {
    extern __shared__ char smem[];
    const uint32_t smem_base = smem_to_u32(smem);
    const int tid = threadIdx.x;
    const int wid = tid >> 5;
    const int lane = tid & 31;
    const int wm = wid & 1;     // 0..1  (M: 64 rows each)
    const int wn = wid >> 1;    // 0..1  (N: 64 cols each)
    const int colTile = blockIdx.x;   // 0..7
    const int rowTile = blockIdx.y;   // 0..63
    const int kz = blockIdx.z;        // 0..1
    const int ktBeg = kz * KT_HALF;

    const uint16_t* aG = g_A + (size_t)rowTile * BM * D_PAD;
    const uint16_t* bG = g_B + (size_t)colTile * BN * D_PAD;

    // loader: 128 threads x 16 iters x 16B. smem rows 0..127 = A, 128..255 = B.
    const int lr = tid >> 3;   // base row 0..15 (stride 16)
    const int lc = tid & 7;    // 16B chunk 0..7 within 128B row

    auto load_stage = [&](int kt, int s) {
        const uint32_t stBase = smem_base + s * STAGE_BYTES;
        const size_t gchunk = (size_t)kt * 8 + lc;   // 16B chunks; row = 1280 chunks
#pragma unroll
        for (int i = 0; i < 16; ++i) {
            const int r = lr + 16 * i;               // 0..255
            const uint32_t off = (uint32_t)(r * 128 + ((lc ^ (r & 7)) << 4));
            const char* src = (r < BM)
                ? reinterpret_cast<const char*>(aG) + ((size_t)r * 1280 + gchunk) * 16
                : reinterpret_cast<const char*>(bG) + ((size_t)(r - BM) * 1280 + gchunk) * 16;
            cp_async16(stBase + off, src);
        }
    };

    // ldmatrix lane addressing (validated R3/R10 scheme)
    const int aLane16 = lane & 15;
    const int aTop = lane >> 4;              // chunk offset 0/1 within the 32B k16
    uint32_t aRowOff[4]; int aXor[4];
#pragma unroll
    for (int mt = 0; mt < 4; ++mt) {
        const int r = wm * 64 + mt * 16 + aLane16;      // A rows 0..127
        aRowOff[mt] = (uint32_t)(r * 128);
        aXor[mt] = r & 7;
    }
    const int bRowInTile = ((lane & 16) >> 1) + (lane & 7);  // +8 for lanes>=16
    const int bTop = (lane >> 3) & 1;        // chunk offset 0/1
    uint32_t bRowOff[4]; int bXor[4];
#pragma unroll
    for (int p = 0; p < 4; ++p) {
        const int r = wn * 64 + p * 16 + bRowInTile;    // B rows 0..127
        bRowOff[p] = (uint32_t)(r * 128);
        bXor[p] = r & 7;
    }

    float acc[4][8][4];
#pragma unroll
    for (int mt = 0; mt < 4; ++mt)
#pragma unroll
        for (int nt = 0; nt < 8; ++nt)
#pragma unroll
            for (int q = 0; q < 4; ++q) acc[mt][nt][q] = 0.0f;

    // prologue: 2 stages in flight
    load_stage(ktBeg + 0, 0); CP_COMMIT();
    load_stage(ktBeg + 1, 1); CP_COMMIT();

    for (int kk = 0; kk < KT_HALF; ++kk) {
        CP_WAIT1();
        __syncthreads();
        if (kk + 2 < KT_HALF) load_stage(ktBeg + kk + 2, (kk + 2) % STAGES);
        CP_COMMIT();

        const uint32_t aBase = smem_base + (kk % STAGES) * STAGE_BYTES;
        const uint32_t bBase = aBase + A_BYTES;
#pragma unroll
        for (int ks = 0; ks < 4; ++ks) {     // 4 x k16 within BK=64
            uint32_t af[4][4];
#pragma unroll
            for (int mt = 0; mt < 4; ++mt) {
                const int chunk = ks * 2 + aTop;
                const uint32_t addr = aBase + aRowOff[mt] + (uint32_t)((chunk ^ aXor[mt]) << 4);
                LDSM_X4(af[mt][0], af[mt][1], af[mt][2], af[mt][3], addr);
            }
            uint32_t bf[8][2];
#pragma unroll
            for (int p = 0; p < 4; ++p) {
                const int chunk = ks * 2 + bTop;
                const uint32_t addr = bBase + bRowOff[p] + (uint32_t)((chunk ^ bXor[p]) << 4);
                LDSM_X4(bf[2 * p][0], bf[2 * p][1], bf[2 * p + 1][0], bf[2 * p + 1][1], addr);
            }
#pragma unroll
            for (int mt = 0; mt < 4; ++mt)
#pragma unroll
                for (int nt = 0; nt < 8; ++nt)
                    MMA_BF16(acc[mt][nt], af[mt], bf[nt]);
        }
    }

    // ---------------- epilogue: store fp32 partials (exact ints) ----
    float* part = g_part + (size_t)kz * N_ROWS * C_PAD;
    const int groupID = lane >> 2;   // 0..7
    const int tig = lane & 3;        // 0..3
#pragma unroll
    for (int mt = 0; mt < 4; ++mt) {
        const int m0 = rowTile * BM + wm * 64 + mt * 16 + groupID;
        float* prow0 = part + (size_t)m0 * C_PAD;
        float* prow1 = part + (size_t)(m0 + 8) * C_PAD;
#pragma unroll
        for (int nt = 0; nt < 8; ++nt) {
            const int c0 = colTile * BN + wn * 64 + nt * 8 + 2 * tig;
            float2 v0, v1;
            v0.x = acc[mt][nt][0]; v0.y = acc[mt][nt][1];
            v1.x = acc[mt][nt][2]; v1.y = acc[mt][nt][3];
            *reinterpret_cast<float2*>(prow0 + c0) = v0;
            *reinterpret_cast<float2*>(prow1 + c0) = v1;
        }
    }
}

// ---------------- combine: out = csum + p0 + p1 ----------------
__global__ void __launch_bounds__(256) combine_kernel(float* __restrict__ out) {
    const int n = blockIdx.x;         // 0..8191
    const int tid = threadIdx.x;
    const float4* p0 = reinterpret_cast<const float4*>(g_part + (size_t)n * C_PAD);
    const float4* p1 = reinterpret_cast<const float4*>(
        g_part + (size_t)(N_ROWS + n) * C_PAD);
    float4* orow = reinterpret_cast<float4*>(out + (size_t)n * C_CLS);
    if (tid < C_CLS / 4) {            // 250 float4 per row
        const int c = tid * 4;
        float4 a = p0[tid];
        float4 b = p1[tid];
        float4 o;
        o.x = (float)g_csum[c + 0] + a.x + b.x;
        o.y = (float)g_csum[c + 1] + a.y + b.y;
        o.z = (float)g_csum[c + 2] + a.z + b.z;
        o.w = (float)g_csum[c + 3] + a.w + b.w;
        orow[tid] = o;
    }
}

// ---------------- launch ----------------
extern "C" void kernel_launch(void* const* d_in, const int* in_sizes, int n_in,
                              void* d_out, int out_size) {
    const float* samples = (const float*)d_in[0];   // [8192, 10000]
    const float* classes = (const float*)d_in[1];   // [1000, 10000]
    float* out = (float*)d_out;                     // [8192, 1000]

    cudaFuncSetAttribute(hd_gemm_kernel, cudaFuncAttributeMaxDynamicSharedMemorySize,
                         SMEM_TOTAL);

    cvt_b_kernel<<<C_PAD, 256>>>(classes);
    cvt_a_kernel<<<N_ROWS, 256>>>(samples);

    dim3 grid(C_PAD / BN, N_ROWS / BM, KSPLIT);  // (8, 64, 2) = 1024 CTAs
    hd_gemm_kernel<<<grid, 128, SMEM_TOTAL>>>();

    combine_kernel<<<N_ROWS, 256>>>(out);
}

// round 13
// speedup vs baseline: 1.0454x; 1.0440x over previous
#include <cuda_runtime.h>
#include <cstdint>

// ---------------- problem dims ----------------
static constexpr int N_ROWS = 8192;    // samples
static constexpr int C_CLS  = 1000;    // classes
static constexpr int D_DIM  = 10000;   // hypervector dim
static constexpr int D_PAD  = 10048;   // padded: 157 * 64 (zeros contribute 0 to dot)
static constexpr int C_PAD  = 1024;    // padded classes (rows >= 1000 are zero)
static constexpr int ROW_CH = D_PAD / 8;   // 1256 16B-chunks per row
static constexpr int DIM_CH = D_DIM / 8;   // 1250 full data chunks

// ---------------- GEMM tiling (bf16) ----------------
static constexpr int BM = 64;
static constexpr int BN = 128;
static constexpr int BK = 64;               // 64 bf16 = 128B rows
static constexpr int KT = D_PAD / BK;       // 157 K-iterations
static constexpr int STAGES = 3;

static constexpr int A_BYTES = BM * BK * 2;            // 8192
static constexpr int STAGE_BYTES = (BM + BN) * BK * 2; // 24576
static constexpr int SMEM_TOTAL = STAGES * STAGE_BYTES; // 73728 -> 3 CTAs/SM

// ---------------- scratch (device globals; no allocation allowed) ----------
__device__ uint16_t g_A[(size_t)N_ROWS * D_PAD];   // 165 MB bf16 {0,1}
__device__ uint16_t g_B[(size_t)C_PAD  * D_PAD];   // 20.6 MB bf16, holds 1-2*B
__device__ int g_csum[C_PAD];

// ---------------- helpers ----------------
__device__ __forceinline__ uint32_t smem_to_u32(const void* p) {
    uint32_t a;
    asm("{ .reg .u64 t; cvta.to.shared.u64 t, %1; cvt.u32.u64 %0, t; }" : "=r"(a) : "l"(p));
    return a;
}

__device__ __forceinline__ void cp_async16(uint32_t smem_addr, const void* gptr) {
    asm volatile("cp.async.cg.shared.global [%0], [%1], 16;"
                 :: "r"(smem_addr), "l"(gptr) : "memory");
}
#define CP_COMMIT() asm volatile("cp.async.commit_group;" ::: "memory")
#define CP_WAIT1()  asm volatile("cp.async.wait_group 1;" ::: "memory")

#define LDSM_X4(r0, r1, r2, r3, addr) \
    asm volatile("ldmatrix.sync.aligned.m8n8.x4.shared.b16 {%0,%1,%2,%3}, [%4];" \
                 : "=r"(r0), "=r"(r1), "=r"(r2), "=r"(r3) : "r"(addr))

// bf16 MMA, fp32 accumulate: D += A(16x16) * B(16x8)^T
#define MMA_BF16(d, a, b) \
    asm volatile("mma.sync.aligned.m16n8k16.row.col.f32.bf16.bf16.f32 " \
                 "{%0,%1,%2,%3}, {%4,%5,%6,%7}, {%8,%9}, {%0,%1,%2,%3};" \
                 : "+f"((d)[0]), "+f"((d)[1]), "+f"((d)[2]), "+f"((d)[3]) \
                 : "r"((a)[0]), "r"((a)[1]), "r"((a)[2]), "r"((a)[3]), \
                   "r"((b)[0]), "r"((b)[1]))

// pack two floats into one u32 holding two bf16 (exact for {-1,0,1})
__device__ __forceinline__ uint32_t packbf2(float lo, float hi) {
    return __byte_perm(__float_as_uint(lo), __float_as_uint(hi), 0x7632);
}

// ---------------- merged conversion: A {0,1}->bf16 ; B -> bf16(1-2B)+csum ----
__global__ void __launch_bounds__(256) cvt_kernel(const float* __restrict__ samples,
                                                  const float* __restrict__ classes) {
    const int bid = blockIdx.x;
    const int tid = threadIdx.x;
    if (bid < N_ROWS) {
        // ---- A row: straight {0,1} -> bf16 ----
        const int row = bid;
        uint4* d4 = reinterpret_cast<uint4*>(g_A + (size_t)row * D_PAD);
        const float4* s4 = reinterpret_cast<const float4*>(samples + (size_t)row * D_DIM);
        for (int i = tid; i < ROW_CH; i += 256) {
            uint4 o;
            if (i < DIM_CH) {
                float4 v0 = s4[i * 2 + 0];
                float4 v1 = s4[i * 2 + 1];
                o.x = packbf2(v0.x, v0.y);
                o.y = packbf2(v0.z, v0.w);
                o.z = packbf2(v1.x, v1.y);
                o.w = packbf2(v1.z, v1.w);
            } else { o.x = 0u; o.y = 0u; o.z = 0u; o.w = 0u; }
            d4[i] = o;
        }
        return;
    }
    // ---- B row: {0,1} -> {-1,+1}, fused csum ----
    const int row = bid - N_ROWS;     // 0..1023
    int acc = 0;
    uint4* d4 = reinterpret_cast<uint4*>(g_B + (size_t)row * D_PAD);
    if (row < C_CLS) {
        const float4* s4 = reinterpret_cast<const float4*>(classes + (size_t)row * D_DIM);
        for (int i = tid; i < ROW_CH; i += 256) {
            uint4 o;
            if (i < DIM_CH) {
                float4 v0 = s4[i * 2 + 0];
                float4 v1 = s4[i * 2 + 1];
                float fs = v0.x + v0.y + v0.z + v0.w + v1.x + v1.y + v1.z + v1.w;
                acc += (int)fs;   // csum: exact
                o.x = packbf2(1.0f - 2.0f * v0.x, 1.0f - 2.0f * v0.y);
                o.y = packbf2(1.0f - 2.0f * v0.z, 1.0f - 2.0f * v0.w);
                o.z = packbf2(1.0f - 2.0f * v1.x, 1.0f - 2.0f * v1.y);
                o.w = packbf2(1.0f - 2.0f * v1.z, 1.0f - 2.0f * v1.w);
            } else { o.x = 0u; o.y = 0u; o.z = 0u; o.w = 0u; }  // pad MUST be 0
            d4[i] = o;
        }
    } else {
        uint4 z; z.x = 0u; z.y = 0u; z.z = 0u; z.w = 0u;
        for (int i = tid; i < ROW_CH; i += 256) d4[i] = z;
    }
    __shared__ int red[8];
    for (int off = 16; off > 0; off >>= 1) acc += __shfl_xor_sync(0xffffffffu, acc, off);
    if ((tid & 31) == 0) red[tid >> 5] = acc;
    __syncthreads();
    if (tid < 8) {
        int v = red[tid];
        for (int off = 4; off > 0; off >>= 1) v += __shfl_xor_sync(0xffu, v, off);
        if (tid == 0) g_csum[row] = v;
    }
}

// ---------------- bf16 GEMM + fused Hamming epilogue (R10 structure) ------
// Block tile 64x128, 128 threads = 4 warps arranged 2 (M) x 2 (N);
// warp tile 32x64. dist = csum[c] + dot(A{0,1}, B'{-1,+1}).
// 3 CTAs/SM, 1024 tiles.
__global__ void __launch_bounds__(128, 3) hd_gemm_kernel(float* __restrict__ out) {
    extern __shared__ char smem[];
    const uint32_t smem_base = smem_to_u32(smem);
    const int tid = threadIdx.x;
    const int wid = tid >> 5;
    const int lane = tid & 31;
    const int wm = wid & 1;     // 0..1  (M: 32 rows each)
    const int wn = wid >> 1;    // 0..1  (N: 64 cols each)
    const int colTile = blockIdx.x;   // 0..7
    const int rowTile = blockIdx.y;   // 0..127

    const uint16_t* aG = g_A + (size_t)rowTile * BM * D_PAD;
    const uint16_t* bG = g_B + (size_t)colTile * BN * D_PAD;

    // loader: 128 threads x 12 iters x 16B. smem rows 0..63 = A, 64..191 = B.
    const int lr = tid >> 3;   // base row 0..15 (stride 16)
    const int lc = tid & 7;    // 16B chunk 0..7 within 128B row

    auto load_stage = [&](int kt, int s) {
        const uint32_t stBase = smem_base + s * STAGE_BYTES;
        const size_t gchunk = (size_t)kt * 8 + lc;   // 16B chunks; row = ROW_CH chunks
#pragma unroll
        for (int i = 0; i < 12; ++i) {
            const int r = lr + 16 * i;               // 0..191
            const uint32_t off = (uint32_t)(r * 128 + ((lc ^ (r & 7)) << 4));
            const char* src = (r < BM)
                ? reinterpret_cast<const char*>(aG) + ((size_t)r * ROW_CH + gchunk) * 16
                : reinterpret_cast<const char*>(bG) + ((size_t)(r - BM) * ROW_CH + gchunk) * 16;
            cp_async16(stBase + off, src);
        }
    };

    // ldmatrix lane addressing (validated R3/R10 scheme)
    const int aLane16 = lane & 15;
    const int aTop = lane >> 4;              // chunk offset 0/1 within the 32B k16
    uint32_t aRowOff[2]; int aXor[2];
#pragma unroll
    for (int mt = 0; mt < 2; ++mt) {
        const int r = wm * 32 + mt * 16 + aLane16;      // A rows 0..63
        aRowOff[mt] = (uint32_t)(r * 128);
        aXor[mt] = r & 7;
    }
    const int bRowInTile = ((lane & 16) >> 1) + (lane & 7);  // +8 for lanes>=16
    const int bTop = (lane >> 3) & 1;        // chunk offset 0/1
    uint32_t bRowOff[4]; int bXor[4];
#pragma unroll
    for (int p = 0; p < 4; ++p) {
        const int r = wn * 64 + p * 16 + bRowInTile;    // B rows 0..127
        bRowOff[p] = (uint32_t)(r * 128);
        bXor[p] = r & 7;
    }

    float acc[2][8][4];
#pragma unroll
    for (int mt = 0; mt < 2; ++mt)
#pragma unroll
        for (int nt = 0; nt < 8; ++nt)
#pragma unroll
            for (int q = 0; q < 4; ++q) acc[mt][nt][q] = 0.0f;

    // prologue: 2 stages in flight
    load_stage(0, 0); CP_COMMIT();
    load_stage(1, 1); CP_COMMIT();

    for (int kt = 0; kt < KT; ++kt) {
        CP_WAIT1();
        __syncthreads();
        if (kt + 2 < KT) load_stage(kt + 2, (kt + 2) % STAGES);
        CP_COMMIT();

        const uint32_t aBase = smem_base + (kt % STAGES) * STAGE_BYTES;
        const uint32_t bBase = aBase + A_BYTES;
#pragma unroll
        for (int ks = 0; ks < 4; ++ks) {     // 4 x k16 within BK=64
            uint32_t af[2][4];
#pragma unroll
            for (int mt = 0; mt < 2; ++mt) {
                const int chunk = ks * 2 + aTop;
                const uint32_t addr = aBase + aRowOff[mt] + (uint32_t)((chunk ^ aXor[mt]) << 4);
                LDSM_X4(af[mt][0], af[mt][1], af[mt][2], af[mt][3], addr);
            }
            uint32_t bf[8][2];
#pragma unroll
            for (int p = 0; p < 4; ++p) {
                const int chunk = ks * 2 + bTop;
                const uint32_t addr = bBase + bRowOff[p] + (uint32_t)((chunk ^ bXor[p]) << 4);
                LDSM_X4(bf[2 * p][0], bf[2 * p][1], bf[2 * p + 1][0], bf[2 * p + 1][1], addr);
            }
#pragma unroll
            for (int mt = 0; mt < 2; ++mt)
#pragma unroll
                for (int nt = 0; nt < 8; ++nt)
                    MMA_BF16(acc[mt][nt], af[mt], bf[nt]);
        }
    }

    // ---------------- epilogue: dist = csum + dot (exact) ----
    const int groupID = lane >> 2;   // 0..7
    const int tig = lane & 3;        // 0..3
#pragma unroll
    for (int mt = 0; mt < 2; ++mt) {
        const int m0 = rowTile * BM + wm * 32 + mt * 16 + groupID;
        float* orow0 = out + (size_t)m0 * C_CLS;
        float* orow1 = out + (size_t)(m0 + 8) * C_CLS;
#pragma unroll
        for (int nt = 0; nt < 8; ++nt) {
            const int c0 = colTile * BN + wn * 64 + nt * 8 + 2 * tig;
            if (c0 < C_CLS) {   // C_CLS even; pair fully valid
                const float cs0 = (float)g_csum[c0];
                const float cs1 = (float)g_csum[c0 + 1];
                float2 v0, v1;
                v0.x = cs0 + acc[mt][nt][0];
                v0.y = cs1 + acc[mt][nt][1];
                v1.x = cs0 + acc[mt][nt][2];
                v1.y = cs1 + acc[mt][nt][3];
                *reinterpret_cast<float2*>(orow0 + c0) = v0;
                *reinterpret_cast<float2*>(orow1 + c0) = v1;
            }
        }
    }
}

// ---------------- launch ----------------
extern "C" void kernel_launch(void* const* d_in, const int* in_sizes, int n_in,
                              void* d_out, int out_size) {
    const float* samples = (const float*)d_in[0];   // [8192, 10000]
    const float* classes = (const float*)d_in[1];   // [1000, 10000]
    float* out = (float*)d_out;                     // [8192, 1000]

    cudaFuncSetAttribute(hd_gemm_kernel, cudaFuncAttributeMaxDynamicSharedMemorySize,
                         SMEM_TOTAL);

    cvt_kernel<<<N_ROWS + C_PAD, 256>>>(samples, classes);

    dim3 grid(C_PAD / BN, N_ROWS / BM);  // (8, 128) = 1024 tiles
    hd_gemm_kernel<<<grid, 128, SMEM_TOTAL>>>(out);
}